// round 17
// baseline (speedup 1.0000x reference)
#include <cuda_runtime.h>
#include <cuda_fp16.h>
#include <cstdint>

// ============================================================================
// QuantLinear: y = x @ (scales*q - zeros) + bias        (sm_100 portable path)
//   x:[32,4096] f32, qweight:[512,11008] i32 (8 nibbles/word along K),
//   scales/zeros/bias:[11008] f32, out:[32,11008] f32
//
//   prep:  g_A[32,4096] = fp16(x) permuted (0,4,1,5,2,6,3,7) within groups of
//          8; partial row sums -> g_Spart[128]; zeroes out[].
//   gemm:  persistent-balanced 2752 units over 296 CTAs, 4-stage cp.async.
//          mma.m16n8k16 fp16->f32. *** L1tex-wavefront diet: warp split
//          (mg,ng) = (row half, 32-col group) -> 1 LDSM.x4/kk (A redundancy
//          halved); Q via 2 LDS.64/kk (kword selected by tg2=j4>>1, column
//          pairs 2*nrow) + shfl.bfly(2) to exchange kwords between tg2
//          partners. ~512 wavefronts/unit vs ~900. ***
//          Epilogue (paired-col map): atomicAdd(out, s*D [+ b - S*(1024*s+z)
//          on chunk-0 segment]).
// ============================================================================

#define KTOT   4096
#define NTOT   11008
#define MTOK   32
#define TILE_N 128
#define TILE_K 128
#define NCHUNK 32
#define NTILES 86
#define UNITS  (NTILES * NCHUNK)  // 2752
#define GRID   296                // 2 x 148 SMs
#define THREADS 256
#define STAGES 4

#define STAGE_BYTES 16384         // A 8192 + Q 8192
#define SM_S (STAGES * STAGE_BYTES)
#define SMEM_TOTAL (SM_S + 128)   // + S[32]

#define OUTN (MTOK * NTOT)        // 352256

__device__ __half g_A[MTOK * KTOT];
__device__ float  g_Spart[128];   // 4 partials per token

// ---------------------------------------------------------------------------
__device__ __forceinline__ uint32_t smem_u32(const void* p) {
    uint32_t a;
    asm("{ .reg .u64 t; cvta.to.shared.u64 t, %1; cvt.u32.u64 %0, t; }"
        : "=r"(a) : "l"(p));
    return a;
}

#define CP16(dst, src) \
    asm volatile("cp.async.cg.shared.global [%0], [%1], 16;" :: "r"(dst), "l"(src))
#define CP_COMMIT() asm volatile("cp.async.commit_group;" ::: "memory")

__device__ __forceinline__ void mma16816(float* d, const uint32_t* a,
                                         uint32_t b0, uint32_t b1) {
    asm volatile(
        "mma.sync.aligned.m16n8k16.row.col.f32.f16.f16.f32 "
        "{%0,%1,%2,%3}, {%4,%5,%6,%7}, {%8,%9}, {%0,%1,%2,%3};"
        : "+f"(d[0]), "+f"(d[1]), "+f"(d[2]), "+f"(d[3])
        : "r"(a[0]), "r"(a[1]), "r"(a[2]), "r"(a[3]), "r"(b0), "r"(b1));
}

__device__ __forceinline__ void ldmx4(uint32_t* a, uint32_t addr) {
    asm volatile("ldmatrix.sync.aligned.m8n8.x4.shared.b16 {%0,%1,%2,%3}, [%4];"
                 : "=r"(a[0]), "=r"(a[1]), "=r"(a[2]), "=r"(a[3]) : "r"(addr));
}

#define LDS64(vx, vy, addr) \
    asm volatile("ld.shared.v2.b32 {%0,%1}, [%2];" : "=r"(vx), "=r"(vy) : "r"(addr))

// ---------------------------------------------------------------------------
// prep: fp16-convert + permute x, partial row sums, and zero out[].
// ---------------------------------------------------------------------------
__global__ void __launch_bounds__(128, 4) prep_kernel(const float* __restrict__ x,
                                                      float* __restrict__ out) {
    int t = blockIdx.x >> 2, sl = blockIdx.x & 3, tid = threadIdx.x;
    int k0 = sl * 1024 + tid * 8;
    const float4* src = (const float4*)(x + (size_t)t * KTOT + k0);
    float4 v0 = src[0];
    float4 v1 = src[1];
    __half h0 = __float2half(v0.x), h1 = __float2half(v0.y);
    __half h2 = __float2half(v0.z), h3 = __float2half(v0.w);
    __half h4 = __float2half(v1.x), h5 = __float2half(v1.y);
    __half h6 = __float2half(v1.z), h7 = __float2half(v1.w);
    float acc = __half2float(h0) + __half2float(h1) + __half2float(h2) +
                __half2float(h3) + __half2float(h4) + __half2float(h5) +
                __half2float(h6) + __half2float(h7);
    uint4 o;
    o.x = (uint32_t)__half_as_ushort(h0) | ((uint32_t)__half_as_ushort(h4) << 16);
    o.y = (uint32_t)__half_as_ushort(h1) | ((uint32_t)__half_as_ushort(h5) << 16);
    o.z = (uint32_t)__half_as_ushort(h2) | ((uint32_t)__half_as_ushort(h6) << 16);
    o.w = (uint32_t)__half_as_ushort(h3) | ((uint32_t)__half_as_ushort(h7) << 16);
    *(uint4*)(g_A + (size_t)t * KTOT + k0) = o;

    // zero out[]
    int gtid = blockIdx.x * 128 + tid;
    const float4 z4 = {0.f, 0.f, 0.f, 0.f};
    for (int i = gtid; i < OUTN / 4; i += 128 * 128)
        ((float4*)out)[i] = z4;

    __shared__ float red[4];
    #pragma unroll
    for (int off = 16; off; off >>= 1) acc += __shfl_down_sync(0xFFFFFFFFu, acc, off);
    if ((tid & 31) == 0) red[tid >> 5] = acc;
    __syncthreads();
    if (tid == 0)
        g_Spart[blockIdx.x] = red[0] + red[1] + red[2] + red[3];
}

// ---------------------------------------------------------------------------
// gemm (persistent balanced, M-split warps, bfly-shared Q)
// ---------------------------------------------------------------------------
__device__ __forceinline__ void issue_unit(uint32_t sb, int tid, int u, int slot,
                                           const int* __restrict__ qw) {
    int nt = u >> 5, cg = u & 31;
    int n0 = nt * TILE_N;
    uint32_t stage = sb + (uint32_t)slot * STAGE_BYTES;
    // A: 32 rows x 16 chunks of 16B (swizzled)
    #pragma unroll
    for (int i = 0; i < 2; i++) {
        int seg = tid + i * 256;
        int r = seg >> 4, cc = seg & 15;
        uint32_t dst = stage + r * 256 + (((uint32_t)cc ^ (uint32_t)(r & 7)) << 4);
        const char* src = (const char*)g_A + ((size_t)r * KTOT + (size_t)cg * TILE_K) * 2 + cc * 16;
        CP16(dst, src);
    }
    // Q: 16 kwords x 32 segs of 16B
    #pragma unroll
    for (int i = 0; i < 2; i++) {
        int seg = tid + i * 256;
        int kw = seg >> 5, ns = seg & 31;
        uint32_t dst = stage + 8192 + kw * 512 + ns * 16;
        const char* src = (const char*)qw + ((size_t)(cg * 16 + kw) * NTOT + n0) * 4 + ns * 16;
        CP16(dst, src);
    }
    CP_COMMIT();
}

__global__ void __launch_bounds__(THREADS, 2) gemm_kernel(
    const int* __restrict__ qw, const float* __restrict__ scales,
    const float* __restrict__ zeros, const float* __restrict__ bias,
    float* __restrict__ out) {
    extern __shared__ __align__(1024) char smem[];
    uint32_t sb = smem_u32(smem);
    int tid = threadIdx.x, wid = tid >> 5, lane = tid & 31;
    float* S_sm = (float*)(smem + SM_S);

    int u0 = (int)(((long long)blockIdx.x * UNITS) / GRID);
    int u1 = (int)(((long long)(blockIdx.x + 1) * UNITS) / GRID);

    if (tid < 32)
        S_sm[tid] = g_Spart[tid * 4] + g_Spart[tid * 4 + 1] +
                    g_Spart[tid * 4 + 2] + g_Spart[tid * 4 + 3];

    // prologue: up to 3 units in flight
    if (u0 + 0 < u1) issue_unit(sb, tid, u0 + 0, 0, qw);
    if (u0 + 1 < u1) issue_unit(sb, tid, u0 + 1, 1, qw);
    if (u0 + 2 < u1) issue_unit(sb, tid, u0 + 2, 2, qw);

    const int mg = wid & 1;              // row half: rows mg*16 .. mg*16+15
    const int ng = wid >> 1;             // 32-col group
    const int lrow = lane & 15;
    const int lcb  = lane >> 4;
    const int j4   = lane & 3;
    const int nrow = lane >> 2;
    const uint32_t sh4 = (uint32_t)(j4 * 4);
    const bool tg2 = (j4 & 2) != 0;      // kword parity owner

    float acc[4][4];
    #pragma unroll
    for (int j = 0; j < 4; j++)
        #pragma unroll
        for (int i = 0; i < 4; i++) acc[j][i] = 0.f;

    int seg_nt = u0 >> 5;
    bool seg_first = ((u0 & 31) == 0);

    for (int u = u0; u < u1; u++) {
        if (u + 2 < u1)      asm volatile("cp.async.wait_group 2;" ::: "memory");
        else if (u + 1 < u1) asm volatile("cp.async.wait_group 1;" ::: "memory");
        else                 asm volatile("cp.async.wait_group 0;" ::: "memory");
        __syncthreads();
        if (u + 3 < u1) issue_unit(sb, tid, u + 3, (u + 3 - u0) & (STAGES - 1), qw);

        uint32_t aBase = sb + (uint32_t)((u - u0) & (STAGES - 1)) * STAGE_BYTES;
        uint32_t qBase = aBase + 8192;
        // thread's Q base: kword parity tg2, col pair (2*nrow, 2*nrow+1)
        uint32_t qn = qBase + (tg2 ? 512u : 0u) + (uint32_t)(ng * 32 + 2 * nrow) * 4;
        uint32_t aRow = aBase + (uint32_t)(mg * 16 + lrow) * 256;

        #pragma unroll
        for (int kk = 0; kk < 8; kk++) {
            uint32_t a[4];
            uint32_t cc = (uint32_t)(kk * 2 + lcb);
            ldmx4(a, aRow + ((cc ^ (uint32_t)(lrow & 7)) << 4));

            // load this thread's kword (2kk + tg2) for its two column pairs
            uint32_t u0x, u0y, u1x, u1y;
            uint32_t qk = qn + (uint32_t)(kk * 1024);
            LDS64(u0x, u0y, qk);           // slices (0,1): cols 2n, 2n+1
            LDS64(u1x, u1y, qk + 64);      // slices (2,3): cols +16

            // exchange with tg2 partner -> have both kwords
            uint32_t v0x = __shfl_xor_sync(0xFFFFFFFFu, u0x, 2);
            uint32_t v0y = __shfl_xor_sync(0xFFFFFFFFu, u0y, 2);
            uint32_t v1x = __shfl_xor_sync(0xFFFFFFFFu, u1x, 2);
            uint32_t v1y = __shfl_xor_sync(0xFFFFFFFFu, u1y, 2);

            uint32_t lo0x = tg2 ? v0x : u0x, hi0x = tg2 ? u0x : v0x;
            uint32_t lo0y = tg2 ? v0y : u0y, hi0y = tg2 ? u0y : v0y;
            uint32_t lo1x = tg2 ? v1x : u1x, hi1x = tg2 ? u1x : v1x;
            uint32_t lo1y = tg2 ? v1y : u1y, hi1y = tg2 ? u1y : v1y;

            uint32_t b00 = ((lo0x >> sh4) & 0x000F000Fu) | 0x64006400u;
            uint32_t b01 = ((hi0x >> sh4) & 0x000F000Fu) | 0x64006400u;
            uint32_t b10 = ((lo0y >> sh4) & 0x000F000Fu) | 0x64006400u;
            uint32_t b11 = ((hi0y >> sh4) & 0x000F000Fu) | 0x64006400u;
            uint32_t b20 = ((lo1x >> sh4) & 0x000F000Fu) | 0x64006400u;
            uint32_t b21 = ((hi1x >> sh4) & 0x000F000Fu) | 0x64006400u;
            uint32_t b30 = ((lo1y >> sh4) & 0x000F000Fu) | 0x64006400u;
            uint32_t b31 = ((hi1y >> sh4) & 0x000F000Fu) | 0x64006400u;

            mma16816(acc[0], a, b00, b01);
            mma16816(acc[1], a, b10, b11);
            mma16816(acc[2], a, b20, b21);
            mma16816(acc[3], a, b30, b31);
        }

        // flush at segment end (tile boundary or range end)
        bool last = (u + 1 == u1);
        if (last || ((u + 1) >> 5) != seg_nt) {
            int n0 = seg_nt * TILE_N;
            #pragma unroll
            for (int j = 0; j < 4; j++) {
                // paired-column map: col = ng*32 + (j&2)*8 + 4*j4 + (j&1)
                int c0 = n0 + ng * 32 + ((j & 2) << 3) + 4 * j4 + (j & 1);
                int c1 = c0 + 2;
                float s0 = __ldg(scales + c0), s1 = __ldg(scales + c1);
                int r0 = mg * 16 + nrow;
                int r1 = r0 + 8;
                float v00 = s0 * acc[j][0];
                float v01 = s1 * acc[j][1];
                float v10 = s0 * acc[j][2];
                float v11 = s1 * acc[j][3];
                if (seg_first) {
                    float z0 = fmaf(1024.f, s0, __ldg(zeros + c0));
                    float z1 = fmaf(1024.f, s1, __ldg(zeros + c1));
                    float b0 = __ldg(bias + c0);
                    float b1 = __ldg(bias + c1);
                    float S0 = S_sm[r0], S1 = S_sm[r1];
                    v00 += b0 - S0 * z0;
                    v01 += b1 - S0 * z1;
                    v10 += b0 - S1 * z0;
                    v11 += b1 - S1 * z1;
                }
                atomicAdd(out + (size_t)r0 * NTOT + c0, v00);
                atomicAdd(out + (size_t)r0 * NTOT + c1, v01);
                atomicAdd(out + (size_t)r1 * NTOT + c0, v10);
                atomicAdd(out + (size_t)r1 * NTOT + c1, v11);
                acc[j][0] = acc[j][1] = acc[j][2] = acc[j][3] = 0.f;
            }
            if (!last) {
                seg_nt = (u + 1) >> 5;
                seg_first = true;        // boundary segments start at chunk 0
            }
        }
    }
}

// ---------------------------------------------------------------------------
extern "C" void kernel_launch(void* const* d_in, const int* in_sizes, int n_in,
                              void* d_out, int out_size) {
    const float* x      = (const float*)d_in[0];
    const int*   qw     = (const int*)d_in[1];
    const float* scales = (const float*)d_in[2];
    const float* zeros  = (const float*)d_in[3];
    const float* bias   = (const float*)d_in[4];
    float* out = (float*)d_out;

    cudaFuncSetAttribute(gemm_kernel, cudaFuncAttributeMaxDynamicSharedMemorySize, SMEM_TOTAL);

    prep_kernel<<<128, 128>>>(x, out);
    gemm_kernel<<<GRID, THREADS, SMEM_TOTAL>>>(qw, scales, zeros, bias, out);
}